// round 4
// baseline (speedup 1.0000x reference)
#include <cuda_runtime.h>
#include <cuda_bf16.h>
#include <math.h>
#include <cstdint>

#define BATCH 4
#define CDIM  256
#define NSP   4096
#define BN2   16777216
#define KTOT  768          // [hi | lo | hi] x [hi | hi | lo]
#define NCHUNK 12          // K chunks of 64

// ---------------------------------------------------------------------------
// Device scratch
// ---------------------------------------------------------------------------
__device__ float g_rowsum[BATCH * NSP];
__device__ float g_colsum[BATCH * NSP];
__device__ __nv_bfloat16 g_P[(size_t)BATCH * NSP * KTOT];
__device__ __nv_bfloat16 g_Q[(size_t)BATCH * NSP * KTOT];
// column top-3 partials: [b][32 rowblocks][3][4096]
__device__ float g_cpart[BATCH * 32 * 3 * NSP];

// ---------------------------------------------------------------------------
// PTX helpers (sm_80-compatible: cp.async, ldmatrix, mma.sync)
// ---------------------------------------------------------------------------
__device__ __forceinline__ uint32_t smem_u32(const void* p) {
    uint32_t a;
    asm("{ .reg .u64 t; cvta.to.shared.u64 t, %1; cvt.u32.u64 %0, t; }"
        : "=r"(a) : "l"(p));
    return a;
}
__device__ __forceinline__ void cp16(uint32_t s, const void* g) {
    asm volatile("cp.async.cg.shared.global [%0], [%1], 16;" :: "r"(s), "l"(g));
}
__device__ __forceinline__ void cp_commit() {
    asm volatile("cp.async.commit_group;");
}
template <int N>
__device__ __forceinline__ void cp_wait() {
    asm volatile("cp.async.wait_group %0;" :: "n"(N));
}
__device__ __forceinline__ void ldmx4(uint32_t* r, uint32_t addr) {
    asm volatile("ldmatrix.sync.aligned.m8n8.x4.shared.b16 {%0,%1,%2,%3}, [%4];"
                 : "=r"(r[0]), "=r"(r[1]), "=r"(r[2]), "=r"(r[3]) : "r"(addr));
}
__device__ __forceinline__ void mma16816(float* d, const uint32_t* a, const uint32_t* b) {
    asm volatile(
        "mma.sync.aligned.m16n8k16.row.col.f32.bf16.bf16.f32 "
        "{%0,%1,%2,%3}, {%4,%5,%6,%7}, {%8,%9}, {%0,%1,%2,%3};"
        : "+f"(d[0]), "+f"(d[1]), "+f"(d[2]), "+f"(d[3])
        : "r"(a[0]), "r"(a[1]), "r"(a[2]), "r"(a[3]), "r"(b[0]), "r"(b[1]));
}

// ---------------------------------------------------------------------------
// Kernel 0: zero accumulators (re-zeroed every replay)
// ---------------------------------------------------------------------------
__global__ void zero_sums_kernel() {
    int i = blockIdx.x * 256 + threadIdx.x;
    g_rowsum[i] = 0.0f;
    g_colsum[i] = 0.0f;
}

// ---------------------------------------------------------------------------
// Kernel 1: prep — L2-normalize over channels, bf16 hi/lo split, transpose to
// K-major [m][768]:  P = [hi | lo | hi],  Q = [hi | hi | lo].
// ---------------------------------------------------------------------------
__global__ __launch_bounds__(256)
void prep_kernel(const float* __restrict__ xp, const float* __restrict__ xq) {
    __shared__ float tile[32][257];
    const int m0 = blockIdx.x * 32;
    const int b  = blockIdx.y;
    const int t  = threadIdx.x;
    const int w  = t >> 5, lane = t & 31;
    const bool isP = (blockIdx.z == 0);
    const float* src = isP ? xp : xq;
    __nv_bfloat16* dst = isP ? g_P : g_Q;

    #pragma unroll 8
    for (int it = 0; it < 32; it++) {
        int c = w + it * 8;
        tile[lane][c] = src[((size_t)b * CDIM + c) * NSP + m0 + lane];
    }
    __syncthreads();

    #pragma unroll
    for (int r = 0; r < 4; r++) {
        int row = w * 4 + r;
        float s = 0.0f;
        #pragma unroll
        for (int k = 0; k < 8; k++) {
            float v = tile[row][lane + 32 * k];
            s = fmaf(v, v, s);
        }
        #pragma unroll
        for (int off = 16; off > 0; off >>= 1)
            s += __shfl_down_sync(0xFFFFFFFFu, s, off);
        float invn = 1.0f / fmaxf(sqrtf(__shfl_sync(0xFFFFFFFFu, s, 0)), 1e-12f);

        size_t obase = ((size_t)b * NSP + m0 + row) * KTOT;
        #pragma unroll
        for (int k = 0; k < 8; k++) {
            int c = lane + 32 * k;
            float v = tile[row][c] * invn;
            __nv_bfloat16 hi = __float2bfloat16(v);
            __nv_bfloat16 lo = __float2bfloat16(v - __bfloat162float(hi));
            dst[obase + c] = hi;
            dst[obase + 256 + c] = isP ? lo : hi;
            dst[obase + 512 + c] = isP ? hi : lo;
        }
    }
}

// ---------------------------------------------------------------------------
// Kernel 2: HMMA GEMM (256x128 tile, K=768 bf16, 512 thr, 3-stage cp.async)
// Warp grid 4(m) x 4(n); warp tile 64x32; mma m16n8k16.
// ---------------------------------------------------------------------------
#define SM_STAGEBASE 2048
#define STAGE_SZ     49152          // A 32KB + B 16KB
#define SMEM_TOTAL   (2048 + 3 * STAGE_SZ)   // 149504

__global__ __launch_bounds__(512, 1)
void gemm_exp_kernel(const float* __restrict__ alpha_p, float* __restrict__ out_e) {
    extern __shared__ char smem[];
    const uint32_t sbase = smem_u32(smem);
    float* srow = (float*)smem;             // 256 floats
    float* scol = (float*)(smem + 1024);    // 128 floats

    const int t = threadIdx.x;
    const int w = t >> 5, lane = t & 31;
    const int b  = blockIdx.z;
    const int i0 = blockIdx.y * 256;
    const int j0 = blockIdx.x * 128;

    if (t < 256) srow[t] = 0.0f;
    if (t < 128) scol[t] = 0.0f;

    const __nv_bfloat16* Abase = g_P + ((size_t)b * NSP + i0) * KTOT;
    const __nv_bfloat16* Bbase = g_Q + ((size_t)b * NSP + j0) * KTOT;

    // async-load chunk c (A 256x64, B 128x64 bf16) into stage s
    auto load_chunk = [&](int c, int s) {
        uint32_t aS = sbase + SM_STAGEBASE + s * STAGE_SZ;
        uint32_t bS = aS + 32768;
        #pragma unroll
        for (int u = 0; u < 4; u++) {
            int f = t + 512 * u;
            uint32_t row = f >> 3, seg = f & 7;
            uint32_t off = row * 128 + ((seg ^ (row & 7)) << 4);
            cp16(aS + off, Abase + (size_t)row * KTOT + c * 64 + seg * 8);
        }
        #pragma unroll
        for (int u = 0; u < 2; u++) {
            int f = t + 512 * u;
            uint32_t row = f >> 3, seg = f & 7;
            uint32_t off = row * 128 + ((seg ^ (row & 7)) << 4);
            cp16(bS + off, Bbase + (size_t)row * KTOT + c * 64 + seg * 8);
        }
    };

    const int wm = w >> 2, wn = w & 3;
    const int r16 = lane & 15, ahi = lane >> 4;
    const int bn  = (lane & 7) + ((lane >> 4) << 3);
    const int bkl = (lane >> 3) & 1;

    float d[4][4][4] = {};

    load_chunk(0, 0); cp_commit();
    load_chunk(1, 1); cp_commit();

    #pragma unroll 1
    for (int c = 0; c < NCHUNK; c++) {
        if (c < NCHUNK - 1) cp_wait<1>(); else cp_wait<0>();
        __syncthreads();
        if (c + 2 < NCHUNK) { load_chunk(c + 2, (c + 2) % 3); cp_commit(); }

        uint32_t aS = sbase + SM_STAGEBASE + (c % 3) * STAGE_SZ;
        uint32_t bS = aS + 32768;

        #pragma unroll
        for (int kk = 0; kk < 4; kk++) {
            uint32_t afr[4][4];
            #pragma unroll
            for (int mt = 0; mt < 4; mt++) {
                uint32_t row = wm * 64 + mt * 16 + r16;
                uint32_t col = (((2 * kk + ahi) ^ (r16 & 7)) << 4);
                ldmx4(afr[mt], aS + row * 128 + col);
            }
            uint32_t bfr[4][2];
            #pragma unroll
            for (int np = 0; np < 2; np++) {
                uint32_t nrow = wn * 32 + np * 16 + bn;
                uint32_t col = (((2 * kk + bkl) ^ (bn & 7)) << 4);
                uint32_t q[4];
                ldmx4(q, bS + nrow * 128 + col);
                bfr[2 * np][0] = q[0]; bfr[2 * np][1] = q[1];
                bfr[2 * np + 1][0] = q[2]; bfr[2 * np + 1][1] = q[3];
            }
            #pragma unroll
            for (int mt = 0; mt < 4; mt++)
                #pragma unroll
                for (int nt = 0; nt < 4; nt++)
                    mma16816(d[mt][nt], afr[mt], bfr[nt]);
        }
        __syncthreads();
    }

    // ---- epilogue: e = exp(alpha * dot); write e; row/col sums ----
    const float alpha = __ldg(alpha_p);
    const int g = lane >> 2, tg = lane & 3;
    float csum[4][2] = {};
    float* outb = out_e + (size_t)b * BN2;

    #pragma unroll
    for (int mt = 0; mt < 4; mt++) {
        float rs0 = 0.0f, rs1 = 0.0f;
        const int row0 = i0 + wm * 64 + mt * 16 + g;
        #pragma unroll
        for (int nt = 0; nt < 4; nt++) {
            float e0 = __expf(d[mt][nt][0] * alpha);
            float e1 = __expf(d[mt][nt][1] * alpha);
            float e2 = __expf(d[mt][nt][2] * alpha);
            float e3 = __expf(d[mt][nt][3] * alpha);
            rs0 += e0 + e1; rs1 += e2 + e3;
            csum[nt][0] += e0 + e2; csum[nt][1] += e1 + e3;
            const int colg = j0 + wn * 32 + nt * 8 + tg * 2;
            *(float2*)(outb + (size_t)row0 * NSP + colg)       = make_float2(e0, e1);
            *(float2*)(outb + (size_t)(row0 + 8) * NSP + colg) = make_float2(e2, e3);
        }
        rs0 += __shfl_xor_sync(0xFFFFFFFFu, rs0, 1);
        rs0 += __shfl_xor_sync(0xFFFFFFFFu, rs0, 2);
        rs1 += __shfl_xor_sync(0xFFFFFFFFu, rs1, 1);
        rs1 += __shfl_xor_sync(0xFFFFFFFFu, rs1, 2);
        if (tg == 0) {
            atomicAdd(&srow[wm * 64 + mt * 16 + g],     rs0);
            atomicAdd(&srow[wm * 64 + mt * 16 + g + 8], rs1);
        }
    }
    #pragma unroll
    for (int nt = 0; nt < 4; nt++)
        #pragma unroll
        for (int cc = 0; cc < 2; cc++) {
            float v = csum[nt][cc];
            v += __shfl_xor_sync(0xFFFFFFFFu, v, 4);
            v += __shfl_xor_sync(0xFFFFFFFFu, v, 8);
            v += __shfl_xor_sync(0xFFFFFFFFu, v, 16);
            if (g == 0) atomicAdd(&scol[wn * 32 + nt * 8 + tg * 2 + cc], v);
        }
    __syncthreads();
    if (t < 256) atomicAdd(&g_rowsum[b * NSP + i0 + t], srow[t]);
    if (t < 128) atomicAdd(&g_colsum[b * NSP + j0 + t], scol[t]);
}

// ---------------------------------------------------------------------------
// top-3 helpers
// ---------------------------------------------------------------------------
__device__ __forceinline__ void top3_push(float v, float& v0, float& v1, float& v2) {
    if (v > v2) {
        if (v > v1) {
            v2 = v1;
            if (v > v0) { v1 = v0; v0 = v; } else { v1 = v; }
        } else v2 = v;
    }
}

// ---------------------------------------------------------------------------
// Kernel 3: finish — fused row pass + transpose + both top-3.
// Block owns 128 complete rows of one batch. For each 32-col tile:
//   phase 1: read e, x = e^2*invr*invc, write x_c (coalesced), smem-stage
//   phase 2: transposed write x_c^T (128B column runs) + column top-3 partial
// Row top-3 kept in registers over full rows -> valp direct.
// Column partials -> g_cpart, reduced by valq_reduce_kernel.
// ---------------------------------------------------------------------------
__global__ __launch_bounds__(256)
void finish_kernel(float* __restrict__ xcq, float* __restrict__ xcp,
                   float* __restrict__ valp) {
    __shared__ float sinvc[NSP];          // 16 KB
    __shared__ float tile[128][36];       // 18 KB, 16B-aligned rows
    const int b   = blockIdx.y;
    const int blk = blockIdx.x;           // 0..31
    const int i0  = blk * 128;
    const int t   = threadIdx.x;
    const int tr  = t >> 3;               // 0..31 (row-within-chunk / col)
    const int tc  = t & 7;                // 0..7

    for (int j = t; j < NSP; j += 256)
        sinvc[j] = 1.0f / g_colsum[b * NSP + j];

    float invr[4];
    #pragma unroll
    for (int ch = 0; ch < 4; ch++)
        invr[ch] = 1.0f / g_rowsum[b * NSP + i0 + 32 * ch + tr];

    float rt0[4], rt1[4], rt2[4];
    #pragma unroll
    for (int ch = 0; ch < 4; ch++) { rt0[ch] = -1e30f; rt1[ch] = -1e30f; rt2[ch] = -1e30f; }

    float* srcb = xcq + (size_t)b * BN2 + (size_t)i0 * NSP;
    float* dstb = xcp + (size_t)b * BN2;
    __syncthreads();

    #pragma unroll 1
    for (int jt = 0; jt < NSP; jt += 32) {
        // ---- phase 1: row-major read/modify/write + stage ----
        const int col4 = jt + tc * 4;
        #pragma unroll
        for (int ch = 0; ch < 4; ch++) {
            const int row = 32 * ch + tr;
            float4 e = *(float4*)(srcb + (size_t)row * NSP + col4);
            float ir = invr[ch];
            float x0 = e.x * e.x * ir * sinvc[col4 + 0];
            float x1 = e.y * e.y * ir * sinvc[col4 + 1];
            float x2 = e.z * e.z * ir * sinvc[col4 + 2];
            float x3 = e.w * e.w * ir * sinvc[col4 + 3];
            *(float4*)(srcb + (size_t)row * NSP + col4) = make_float4(x0, x1, x2, x3);
            *(float4*)(&tile[row][tc * 4]) = make_float4(x0, x1, x2, x3);
            top3_push(x0, rt0[ch], rt1[ch], rt2[ch]);
            top3_push(x1, rt0[ch], rt1[ch], rt2[ch]);
            top3_push(x2, rt0[ch], rt1[ch], rt2[ch]);
            top3_push(x3, rt0[ch], rt1[ch], rt2[ch]);
        }
        __syncthreads();

        // ---- phase 2: transposed write + column top-3 ----
        const int col = tr;               // 0..31 -> global column jt+col
        float c0 = -1e30f, c1 = -1e30f, c2 = -1e30f;
        #pragma unroll
        for (int ch = 0; ch < 4; ch++) {
            const int r4 = 32 * ch + tc * 4;
            float v0 = tile[r4 + 0][col];
            float v1 = tile[r4 + 1][col];
            float v2 = tile[r4 + 2][col];
            float v3 = tile[r4 + 3][col];
            *(float4*)(dstb + (size_t)(jt + col) * NSP + i0 + r4) =
                make_float4(v0, v1, v2, v3);
            top3_push(v0, c0, c1, c2);
            top3_push(v1, c0, c1, c2);
            top3_push(v2, c0, c1, c2);
            top3_push(v3, c0, c1, c2);
        }
        #pragma unroll
        for (int off = 4; off > 0; off >>= 1) {
            float u0 = __shfl_xor_sync(0xFFFFFFFFu, c0, off);
            float u1 = __shfl_xor_sync(0xFFFFFFFFu, c1, off);
            float u2 = __shfl_xor_sync(0xFFFFFFFFu, c2, off);
            top3_push(u0, c0, c1, c2);
            top3_push(u1, c0, c1, c2);
            top3_push(u2, c0, c1, c2);
        }
        if (tc == 0) {
            const int base = (b * 32 + blk) * 3;
            g_cpart[(base + 0) * NSP + jt + col] = c0;
            g_cpart[(base + 1) * NSP + jt + col] = c1;
            g_cpart[(base + 2) * NSP + jt + col] = c2;
        }
        __syncthreads();
    }

    // ---- row top-3 merge (8 threads per row: lanes sharing t>>3) ----
    #pragma unroll
    for (int ch = 0; ch < 4; ch++) {
        float v0 = rt0[ch], v1 = rt1[ch], v2 = rt2[ch];
        #pragma unroll
        for (int off = 4; off > 0; off >>= 1) {
            float u0 = __shfl_xor_sync(0xFFFFFFFFu, v0, off);
            float u1 = __shfl_xor_sync(0xFFFFFFFFu, v1, off);
            float u2 = __shfl_xor_sync(0xFFFFFFFFu, v2, off);
            top3_push(u0, v0, v1, v2);
            top3_push(u1, v0, v1, v2);
            top3_push(u2, v0, v1, v2);
        }
        if (tc == 0) {
            const int row = i0 + 32 * ch + tr;
            valp[b * 3 * NSP + 0 * NSP + row] = v0;
            valp[b * 3 * NSP + 1 * NSP + row] = v1;
            valp[b * 3 * NSP + 2 * NSP + row] = v2;
        }
    }
}

// ---------------------------------------------------------------------------
// Kernel 4: reduce column top-3 partials -> valq
// ---------------------------------------------------------------------------
__global__ __launch_bounds__(256)
void valq_reduce_kernel(float* __restrict__ valq) {
    const int b = blockIdx.y;
    const int j = blockIdx.x * 256 + threadIdx.x;
    float v0 = -1e30f, v1 = -1e30f, v2 = -1e30f;
    #pragma unroll 4
    for (int blk = 0; blk < 32; blk++) {
        const int base = (b * 32 + blk) * 3;
        top3_push(g_cpart[(base + 0) * NSP + j], v0, v1, v2);
        top3_push(g_cpart[(base + 1) * NSP + j], v0, v1, v2);
        top3_push(g_cpart[(base + 2) * NSP + j], v0, v1, v2);
    }
    valq[b * 3 * NSP + 0 * NSP + j] = v0;
    valq[b * 3 * NSP + 1 * NSP + j] = v1;
    valq[b * 3 * NSP + 2 * NSP + j] = v2;
}

// ---------------------------------------------------------------------------
extern "C" void kernel_launch(void* const* d_in, const int* in_sizes, int n_in,
                              void* d_out, int out_size) {
    const float* xp    = (const float*)d_in[0];
    const float* xq    = (const float*)d_in[1];
    const float* alpha = (const float*)d_in[2];

    float* valp = (float*)d_out;
    float* valq = valp + BATCH * 3 * NSP;
    float* xcp  = valq + BATCH * 3 * NSP;
    float* xcq  = xcp + (size_t)BATCH * BN2;

    cudaFuncSetAttribute(gemm_exp_kernel,
                         cudaFuncAttributeMaxDynamicSharedMemorySize, SMEM_TOTAL);

    zero_sums_kernel<<<64, 256>>>();
    prep_kernel<<<dim3(128, BATCH, 2), 256>>>(xp, xq);
    gemm_exp_kernel<<<dim3(32, 16, BATCH), 512, SMEM_TOTAL>>>(alpha, xcq);
    finish_kernel<<<dim3(32, BATCH), 256>>>(xcq, xcp, valp);
    valq_reduce_kernel<<<dim3(16, BATCH), 256>>>(valq);
}

// round 5
// speedup vs baseline: 1.7558x; 1.7558x over previous
#include <cuda_runtime.h>
#include <cuda_bf16.h>
#include <math.h>
#include <cstdint>

#define BATCH 4
#define CDIM  256
#define NSP   4096
#define BN2   16777216
#define KTOT  768          // [hi | lo | hi] x [hi | hi | lo]
#define NCHUNK 12          // K chunks of 64

// ---------------------------------------------------------------------------
// Device scratch
// ---------------------------------------------------------------------------
__device__ float g_rowsum[BATCH * NSP];
__device__ float g_colsum[BATCH * NSP];
__device__ __nv_bfloat16 g_P[(size_t)BATCH * NSP * KTOT];
__device__ __nv_bfloat16 g_Q[(size_t)BATCH * NSP * KTOT];
// top-3 partials
__device__ float g_cpart[BATCH * 32 * 3 * NSP];   // [b][rowblock][3][col]
__device__ float g_rpart[BATCH * 8  * 3 * NSP];   // [b][colchunk][3][row]

// ---------------------------------------------------------------------------
// PTX helpers (sm_80-compatible: cp.async, ldmatrix, mma.sync)
// ---------------------------------------------------------------------------
__device__ __forceinline__ uint32_t smem_u32(const void* p) {
    uint32_t a;
    asm("{ .reg .u64 t; cvta.to.shared.u64 t, %1; cvt.u32.u64 %0, t; }"
        : "=r"(a) : "l"(p));
    return a;
}
__device__ __forceinline__ void cp16(uint32_t s, const void* g) {
    asm volatile("cp.async.cg.shared.global [%0], [%1], 16;" :: "r"(s), "l"(g));
}
__device__ __forceinline__ void cp_commit() {
    asm volatile("cp.async.commit_group;");
}
template <int N>
__device__ __forceinline__ void cp_wait() {
    asm volatile("cp.async.wait_group %0;" :: "n"(N));
}
__device__ __forceinline__ void ldmx4(uint32_t* r, uint32_t addr) {
    asm volatile("ldmatrix.sync.aligned.m8n8.x4.shared.b16 {%0,%1,%2,%3}, [%4];"
                 : "=r"(r[0]), "=r"(r[1]), "=r"(r[2]), "=r"(r[3]) : "r"(addr));
}
__device__ __forceinline__ void mma16816(float* d, const uint32_t* a, const uint32_t* b) {
    asm volatile(
        "mma.sync.aligned.m16n8k16.row.col.f32.bf16.bf16.f32 "
        "{%0,%1,%2,%3}, {%4,%5,%6,%7}, {%8,%9}, {%0,%1,%2,%3};"
        : "+f"(d[0]), "+f"(d[1]), "+f"(d[2]), "+f"(d[3])
        : "r"(a[0]), "r"(a[1]), "r"(a[2]), "r"(a[3]), "r"(b[0]), "r"(b[1]));
}

// ---------------------------------------------------------------------------
// Kernel 0: zero accumulators (re-zeroed every replay)
// ---------------------------------------------------------------------------
__global__ void zero_sums_kernel() {
    int i = blockIdx.x * 256 + threadIdx.x;
    g_rowsum[i] = 0.0f;
    g_colsum[i] = 0.0f;
}

// ---------------------------------------------------------------------------
// Kernel 1: prep — L2-normalize over channels, bf16 hi/lo split, transpose to
// K-major [m][768]:  P = [hi | lo | hi],  Q = [hi | hi | lo].
// ---------------------------------------------------------------------------
__global__ __launch_bounds__(256)
void prep_kernel(const float* __restrict__ xp, const float* __restrict__ xq) {
    __shared__ float tile[32][257];
    const int m0 = blockIdx.x * 32;
    const int b  = blockIdx.y;
    const int t  = threadIdx.x;
    const int w  = t >> 5, lane = t & 31;
    const bool isP = (blockIdx.z == 0);
    const float* src = isP ? xp : xq;
    __nv_bfloat16* dst = isP ? g_P : g_Q;

    #pragma unroll 8
    for (int it = 0; it < 32; it++) {
        int c = w + it * 8;
        tile[lane][c] = src[((size_t)b * CDIM + c) * NSP + m0 + lane];
    }
    __syncthreads();

    #pragma unroll
    for (int r = 0; r < 4; r++) {
        int row = w * 4 + r;
        float s = 0.0f;
        #pragma unroll
        for (int k = 0; k < 8; k++) {
            float v = tile[row][lane + 32 * k];
            s = fmaf(v, v, s);
        }
        #pragma unroll
        for (int off = 16; off > 0; off >>= 1)
            s += __shfl_down_sync(0xFFFFFFFFu, s, off);
        float invn = 1.0f / fmaxf(sqrtf(__shfl_sync(0xFFFFFFFFu, s, 0)), 1e-12f);

        size_t obase = ((size_t)b * NSP + m0 + row) * KTOT;
        #pragma unroll
        for (int k = 0; k < 8; k++) {
            int c = lane + 32 * k;
            float v = tile[row][c] * invn;
            __nv_bfloat16 hi = __float2bfloat16(v);
            __nv_bfloat16 lo = __float2bfloat16(v - __bfloat162float(hi));
            dst[obase + c] = hi;
            dst[obase + 256 + c] = isP ? lo : hi;
            dst[obase + 512 + c] = isP ? hi : lo;
        }
    }
}

// ---------------------------------------------------------------------------
// Kernel 2: HMMA GEMM (128x128 tile, K=768 bf16) + exp epilogue.  [R3 config]
// Warp grid 2(m) x 4(n); warp tile 64x32; 2 CTAs/SM; double buffer.
// ---------------------------------------------------------------------------
#define SMEM_BUFS  1024
#define SMEM_TOTAL (1024 + 4 * 16384)

__global__ __launch_bounds__(256, 2)
void gemm_exp_kernel(const float* __restrict__ alpha_p, float* __restrict__ out_e) {
    extern __shared__ char smem[];
    const uint32_t sbase = smem_u32(smem);
    float* srow = (float*)smem;
    float* scol = (float*)(smem + 512);

    const int t = threadIdx.x;
    const int w = t >> 5, lane = t & 31;
    const int b  = blockIdx.z;
    const int i0 = blockIdx.y * 128;
    const int j0 = blockIdx.x * 128;

    if (t < 128) { srow[t] = 0.0f; scol[t] = 0.0f; }

    const __nv_bfloat16* Abase = g_P + ((size_t)b * NSP + i0) * KTOT;
    const __nv_bfloat16* Bbase = g_Q + ((size_t)b * NSP + j0) * KTOT;

    auto load_chunk = [&](int c, int buf) {
        uint32_t aS = sbase + SMEM_BUFS + buf * 32768;
        uint32_t bS = aS + 16384;
        #pragma unroll
        for (int u = 0; u < 4; u++) {
            int f = t + 256 * u;
            uint32_t row = f >> 3, seg = f & 7;
            uint32_t off = row * 128 + ((seg ^ (row & 7)) << 4);
            cp16(aS + off, Abase + (size_t)row * KTOT + c * 64 + seg * 8);
            cp16(bS + off, Bbase + (size_t)row * KTOT + c * 64 + seg * 8);
        }
    };

    const int wm = w >> 2, wn = w & 3;
    const int r16 = lane & 15, ahi = lane >> 4;
    const int bn  = (lane & 7) + ((lane >> 4) << 3);
    const int bkl = (lane >> 3) & 1;

    float d[4][4][4] = {};

    load_chunk(0, 0);
    cp_commit();

    #pragma unroll 1
    for (int c = 0; c < NCHUNK; c++) {
        if (c < NCHUNK - 1) { load_chunk(c + 1, (c + 1) & 1); cp_commit(); }
        if (c < NCHUNK - 1) cp_wait<1>(); else cp_wait<0>();
        __syncthreads();

        uint32_t aS = sbase + SMEM_BUFS + (c & 1) * 32768;
        uint32_t bS = aS + 16384;

        #pragma unroll
        for (int kk = 0; kk < 4; kk++) {
            uint32_t afr[4][4];
            #pragma unroll
            for (int mt = 0; mt < 4; mt++) {
                uint32_t row = wm * 64 + mt * 16 + r16;
                uint32_t col = (((2 * kk + ahi) ^ (r16 & 7)) << 4);
                ldmx4(afr[mt], aS + row * 128 + col);
            }
            uint32_t bfr[4][2];
            #pragma unroll
            for (int np = 0; np < 2; np++) {
                uint32_t nrow = wn * 32 + np * 16 + bn;
                uint32_t col = (((2 * kk + bkl) ^ (bn & 7)) << 4);
                uint32_t q[4];
                ldmx4(q, bS + nrow * 128 + col);
                bfr[2 * np][0] = q[0]; bfr[2 * np][1] = q[1];
                bfr[2 * np + 1][0] = q[2]; bfr[2 * np + 1][1] = q[3];
            }
            #pragma unroll
            for (int mt = 0; mt < 4; mt++)
                #pragma unroll
                for (int nt = 0; nt < 4; nt++)
                    mma16816(d[mt][nt], afr[mt], bfr[nt]);
        }
        __syncthreads();
    }

    const float alpha = __ldg(alpha_p);
    const int g = lane >> 2, tg = lane & 3;
    float csum[4][2] = {};
    float* outb = out_e + (size_t)b * BN2;

    #pragma unroll
    for (int mt = 0; mt < 4; mt++) {
        float rs0 = 0.0f, rs1 = 0.0f;
        const int row0 = i0 + wm * 64 + mt * 16 + g;
        #pragma unroll
        for (int nt = 0; nt < 4; nt++) {
            float e0 = __expf(d[mt][nt][0] * alpha);
            float e1 = __expf(d[mt][nt][1] * alpha);
            float e2 = __expf(d[mt][nt][2] * alpha);
            float e3 = __expf(d[mt][nt][3] * alpha);
            rs0 += e0 + e1; rs1 += e2 + e3;
            csum[nt][0] += e0 + e2; csum[nt][1] += e1 + e3;
            const int colg = j0 + wn * 32 + nt * 8 + tg * 2;
            *(float2*)(outb + (size_t)row0 * NSP + colg)       = make_float2(e0, e1);
            *(float2*)(outb + (size_t)(row0 + 8) * NSP + colg) = make_float2(e2, e3);
        }
        rs0 += __shfl_xor_sync(0xFFFFFFFFu, rs0, 1);
        rs0 += __shfl_xor_sync(0xFFFFFFFFu, rs0, 2);
        rs1 += __shfl_xor_sync(0xFFFFFFFFu, rs1, 1);
        rs1 += __shfl_xor_sync(0xFFFFFFFFu, rs1, 2);
        if (tg == 0) {
            atomicAdd(&srow[wm * 64 + mt * 16 + g],     rs0);
            atomicAdd(&srow[wm * 64 + mt * 16 + g + 8], rs1);
        }
    }
    #pragma unroll
    for (int nt = 0; nt < 4; nt++)
        #pragma unroll
        for (int cc = 0; cc < 2; cc++) {
            float v = csum[nt][cc];
            v += __shfl_xor_sync(0xFFFFFFFFu, v, 4);
            v += __shfl_xor_sync(0xFFFFFFFFu, v, 8);
            v += __shfl_xor_sync(0xFFFFFFFFu, v, 16);
            if (g == 0) atomicAdd(&scol[wn * 32 + nt * 8 + tg * 2 + cc], v);
        }
    __syncthreads();
    if (t < 128) {
        atomicAdd(&g_rowsum[b * NSP + i0 + t], srow[t]);
        atomicAdd(&g_colsum[b * NSP + j0 + t], scol[t]);
    }
}

// ---------------------------------------------------------------------------
// top-3 helpers
// ---------------------------------------------------------------------------
__device__ __forceinline__ void top3_push(float v, float& v0, float& v1, float& v2) {
    if (v > v2) {
        if (v > v1) {
            v2 = v1;
            if (v > v0) { v1 = v0; v0 = v; } else { v1 = v; }
        } else v2 = v;
    }
}

// ---------------------------------------------------------------------------
// Kernel 3: finish — fused row pass + transpose + partial top-3s.
// Block = 128 rows x 512 cols of one batch (grid 8 x 32 x 4 = 1024 CTAs).
// Row top-3 partials -> g_rpart; column top-3 partials -> g_cpart.
// ---------------------------------------------------------------------------
__global__ __launch_bounds__(256)
void finish_kernel(float* __restrict__ xcq, float* __restrict__ xcp) {
    __shared__ float sinvc[512];
    __shared__ float tile[128][36];
    const int b   = blockIdx.z;
    const int blk = blockIdx.y;           // rowblock 0..31
    const int cc  = blockIdx.x;           // colchunk 0..7
    const int i0  = blk * 128;
    const int j0  = cc * 512;
    const int t   = threadIdx.x;
    const int tr  = t >> 3;               // 0..31
    const int tc  = t & 7;                // 0..7

    if (t < 512 / 2) {
        sinvc[2 * t]     = 1.0f / g_colsum[b * NSP + j0 + 2 * t];
        sinvc[2 * t + 1] = 1.0f / g_colsum[b * NSP + j0 + 2 * t + 1];
    }

    float invr[4];
    #pragma unroll
    for (int ch = 0; ch < 4; ch++)
        invr[ch] = 1.0f / g_rowsum[b * NSP + i0 + 32 * ch + tr];

    float rt0[4], rt1[4], rt2[4];
    #pragma unroll
    for (int ch = 0; ch < 4; ch++) { rt0[ch] = -1e30f; rt1[ch] = -1e30f; rt2[ch] = -1e30f; }

    float* srcb = xcq + (size_t)b * BN2 + (size_t)i0 * NSP;
    float* dstb = xcp + (size_t)b * BN2;
    __syncthreads();

    #pragma unroll 1
    for (int jl = 0; jl < 512; jl += 32) {
        const int jt = j0 + jl;
        // ---- phase 1: row-major read/modify/write + stage ----
        const int col4 = jt + tc * 4;
        #pragma unroll
        for (int ch = 0; ch < 4; ch++) {
            const int row = 32 * ch + tr;
            float4 e = *(float4*)(srcb + (size_t)row * NSP + col4);
            float ir = invr[ch];
            float x0 = e.x * e.x * ir * sinvc[jl + tc * 4 + 0];
            float x1 = e.y * e.y * ir * sinvc[jl + tc * 4 + 1];
            float x2 = e.z * e.z * ir * sinvc[jl + tc * 4 + 2];
            float x3 = e.w * e.w * ir * sinvc[jl + tc * 4 + 3];
            *(float4*)(srcb + (size_t)row * NSP + col4) = make_float4(x0, x1, x2, x3);
            *(float4*)(&tile[row][tc * 4]) = make_float4(x0, x1, x2, x3);
            top3_push(x0, rt0[ch], rt1[ch], rt2[ch]);
            top3_push(x1, rt0[ch], rt1[ch], rt2[ch]);
            top3_push(x2, rt0[ch], rt1[ch], rt2[ch]);
            top3_push(x3, rt0[ch], rt1[ch], rt2[ch]);
        }
        __syncthreads();

        // ---- phase 2: transposed write + column top-3 partials ----
        const int col = tr;
        float c0 = -1e30f, c1 = -1e30f, c2 = -1e30f;
        #pragma unroll
        for (int ch = 0; ch < 4; ch++) {
            const int r4 = 32 * ch + tc * 4;
            float v0 = tile[r4 + 0][col];
            float v1 = tile[r4 + 1][col];
            float v2 = tile[r4 + 2][col];
            float v3 = tile[r4 + 3][col];
            *(float4*)(dstb + (size_t)(jt + col) * NSP + i0 + r4) =
                make_float4(v0, v1, v2, v3);
            top3_push(v0, c0, c1, c2);
            top3_push(v1, c0, c1, c2);
            top3_push(v2, c0, c1, c2);
            top3_push(v3, c0, c1, c2);
        }
        #pragma unroll
        for (int off = 4; off > 0; off >>= 1) {
            float u0 = __shfl_xor_sync(0xFFFFFFFFu, c0, off);
            float u1 = __shfl_xor_sync(0xFFFFFFFFu, c1, off);
            float u2 = __shfl_xor_sync(0xFFFFFFFFu, c2, off);
            top3_push(u0, c0, c1, c2);
            top3_push(u1, c0, c1, c2);
            top3_push(u2, c0, c1, c2);
        }
        if (tc == 0) {
            const int base = (b * 32 + blk) * 3;
            g_cpart[(base + 0) * NSP + jt + col] = c0;
            g_cpart[(base + 1) * NSP + jt + col] = c1;
            g_cpart[(base + 2) * NSP + jt + col] = c2;
        }
        __syncthreads();
    }

    // ---- row top-3 partials over this 512-col chunk ----
    #pragma unroll
    for (int ch = 0; ch < 4; ch++) {
        float v0 = rt0[ch], v1 = rt1[ch], v2 = rt2[ch];
        #pragma unroll
        for (int off = 4; off > 0; off >>= 1) {
            float u0 = __shfl_xor_sync(0xFFFFFFFFu, v0, off);
            float u1 = __shfl_xor_sync(0xFFFFFFFFu, v1, off);
            float u2 = __shfl_xor_sync(0xFFFFFFFFu, v2, off);
            top3_push(u0, v0, v1, v2);
            top3_push(u1, v0, v1, v2);
            top3_push(u2, v0, v1, v2);
        }
        if (tc == 0) {
            const int base = (b * 8 + cc) * 3;
            const int row = i0 + 32 * ch + tr;
            g_rpart[(base + 0) * NSP + row] = v0;
            g_rpart[(base + 1) * NSP + row] = v1;
            g_rpart[(base + 2) * NSP + row] = v2;
        }
    }
}

// ---------------------------------------------------------------------------
// Kernel 4: reduce partials -> valp (z=0) and valq (z=1)
// ---------------------------------------------------------------------------
__global__ __launch_bounds__(256)
void topk_reduce_kernel(float* __restrict__ valp, float* __restrict__ valq) {
    const int b = blockIdx.y;
    const int j = blockIdx.x * 256 + threadIdx.x;
    float v0 = -1e30f, v1 = -1e30f, v2 = -1e30f;
    if (blockIdx.z == 0) {
        #pragma unroll 2
        for (int p = 0; p < 8; p++) {
            const int base = (b * 8 + p) * 3;
            top3_push(g_rpart[(base + 0) * NSP + j], v0, v1, v2);
            top3_push(g_rpart[(base + 1) * NSP + j], v0, v1, v2);
            top3_push(g_rpart[(base + 2) * NSP + j], v0, v1, v2);
        }
        valp[b * 3 * NSP + 0 * NSP + j] = v0;
        valp[b * 3 * NSP + 1 * NSP + j] = v1;
        valp[b * 3 * NSP + 2 * NSP + j] = v2;
    } else {
        #pragma unroll 2
        for (int p = 0; p < 32; p++) {
            const int base = (b * 32 + p) * 3;
            top3_push(g_cpart[(base + 0) * NSP + j], v0, v1, v2);
            top3_push(g_cpart[(base + 1) * NSP + j], v0, v1, v2);
            top3_push(g_cpart[(base + 2) * NSP + j], v0, v1, v2);
        }
        valq[b * 3 * NSP + 0 * NSP + j] = v0;
        valq[b * 3 * NSP + 1 * NSP + j] = v1;
        valq[b * 3 * NSP + 2 * NSP + j] = v2;
    }
}

// ---------------------------------------------------------------------------
extern "C" void kernel_launch(void* const* d_in, const int* in_sizes, int n_in,
                              void* d_out, int out_size) {
    const float* xp    = (const float*)d_in[0];
    const float* xq    = (const float*)d_in[1];
    const float* alpha = (const float*)d_in[2];

    float* valp = (float*)d_out;
    float* valq = valp + BATCH * 3 * NSP;
    float* xcp  = valq + BATCH * 3 * NSP;
    float* xcq  = xcp + (size_t)BATCH * BN2;

    cudaFuncSetAttribute(gemm_exp_kernel,
                         cudaFuncAttributeMaxDynamicSharedMemorySize, SMEM_TOTAL);

    zero_sums_kernel<<<64, 256>>>();
    prep_kernel<<<dim3(128, BATCH, 2), 256>>>(xp, xq);
    gemm_exp_kernel<<<dim3(32, 32, BATCH), 256, SMEM_TOTAL>>>(alpha, xcq);
    finish_kernel<<<dim3(8, 32, BATCH), 256>>>(xcq, xcp);
    topk_reduce_kernel<<<dim3(16, BATCH, 2), 256>>>(valp, valq);
}